// round 1
// baseline (speedup 1.0000x reference)
#include <cuda_runtime.h>

#define BATCH 4
#define SEQ   4096
#define EDIM  256
#define NTOK  (BATCH*SEQ)

// Scratch (device globals: no allocation allowed in kernel_launch)
__device__ float g_Q[NTOK*EDIM];
__device__ float g_K[NTOK*EDIM];
__device__ float g_V[NTOK*EDIM];
__device__ float g_O[NTOK*EDIM];

// ---------------------------------------------------------------------------
// Fused QKV projection: Y[m,n] = sum_k X[m,k] * W[n,k] + b[n]
// grid = (NTOK/64, 12): blockIdx.y selects {Wq,Wk,Wv} x 4 column tiles of 64.
// CTA tile 64x64, 256 threads, 4x4 micro-tile. Smem tiles stored k-major so
// the inner loop is two float4 LDS (one warp-broadcast) per 16 FFMA.
// ---------------------------------------------------------------------------
__global__ __launch_bounds__(256) void proj_kernel(
    const float* __restrict__ X,
    const float* __restrict__ Wq, const float* __restrict__ bq,
    const float* __restrict__ Wk, const float* __restrict__ bk,
    const float* __restrict__ Wv, const float* __restrict__ bv)
{
    __shared__ __align__(16) float Xt[32*68];
    __shared__ __align__(16) float Wt[32*68];

    const int mt    = blockIdx.x;
    const int nt    = blockIdx.y;
    const int which = nt >> 2;           // 0=q 1=k 2=v
    const int n0    = (nt & 3) << 6;
    const int m0    = mt << 6;

    const float* W    = (which == 0) ? Wq : (which == 1) ? Wk : Wv;
    const float* bias = (which == 0) ? bq : (which == 1) ? bk : bv;
    float*       Y    = (which == 0) ? g_Q : (which == 1) ? g_K : g_V;

    const int tid = threadIdx.x;
    const int tx  = tid & 15;
    const int ty  = tid >> 4;

    float acc[4][4] = {};

    for (int kk = 0; kk < EDIM; kk += 32) {
        __syncthreads();
        #pragma unroll
        for (int e = 0; e < 8; e++) {
            int idx = tid + e*256;
            int m = idx >> 5;
            int k = idx & 31;
            Xt[k*68 + m] = X[(m0+m)*EDIM + kk + k];
            Wt[k*68 + m] = W[(n0+m)*EDIM + kk + k];
        }
        __syncthreads();
        #pragma unroll 8
        for (int k = 0; k < 32; k++) {
            float4 a4 = *(const float4*)(Xt + k*68 + 4*ty);
            float4 b4 = *(const float4*)(Wt + k*68 + 4*tx);
            float a[4] = {a4.x, a4.y, a4.z, a4.w};
            float b[4] = {b4.x, b4.y, b4.z, b4.w};
            #pragma unroll
            for (int i = 0; i < 4; i++)
                #pragma unroll
                for (int j = 0; j < 4; j++)
                    acc[i][j] = fmaf(a[i], b[j], acc[i][j]);
        }
    }

    float4 bv4 = *(const float4*)(bias + n0 + 4*tx);
    float bb[4] = {bv4.x, bv4.y, bv4.z, bv4.w};
    #pragma unroll
    for (int i = 0; i < 4; i++) {
        float4 o;
        o.x = acc[i][0] + bb[0];
        o.y = acc[i][1] + bb[1];
        o.z = acc[i][2] + bb[2];
        o.w = acc[i][3] + bb[3];
        *(float4*)(Y + (m0 + 4*ty + i)*EDIM + n0 + 4*tx) = o;
    }
}

// ---------------------------------------------------------------------------
// Flash attention over one batch, 64 queries per CTA, 64-key tiles,
// online softmax, fused residual-add + LayerNorm epilogue.
// Thread (tx,ty) owns query rows 4*ty+i and dim columns dc*64 + 4*tx+j.
// Smem: Qt (full Q tile, k-major), Ss (P tile), Wb (K-chunk / V-chunk work).
// ---------------------------------------------------------------------------
__global__ __launch_bounds__(256, 2) void flash_kernel(
    const float* __restrict__ RES,
    const float* __restrict__ gamma, const float* __restrict__ beta,
    float* __restrict__ OUT)
{
    extern __shared__ float sm[];
    float* Qt = sm;                 // 256*68 (k-major: Qt[k*68 + row])
    float* Ss = Qt + 256*68;        // 64*65  (Ss[row*65 + key])
    float* Wb = Ss + 64*65;         // 64*68  work tile
    float* rm = Wb + 64*68;         // running max [64]
    float* rl = rm + 64;            // running sum [64]
    float* ra = rl + 64;            // alpha      [64]

    const int qt   = blockIdx.x;
    const int b    = blockIdx.y;
    const int q0   = qt << 6;
    const int base = b * SEQ * EDIM;
    const float* Qb = g_Q + base;
    const float* Kb = g_K + base;
    const float* Vb = g_V + base;

    const int tid = threadIdx.x;
    const int tx  = tid & 15;
    const int ty  = tid >> 4;

    // Load Q tile [64 x 256] transposed to k-major (coalesced gmem reads)
    #pragma unroll 8
    for (int r = 0; r < 64; r++) {
        Qt[tid*68 + r] = Qb[(q0 + r)*EDIM + tid];
    }
    if (tid < 64) { rm[tid] = -1e30f; rl[tid] = 0.0f; }

    float acc[4][16];
    #pragma unroll
    for (int i = 0; i < 4; i++)
        #pragma unroll
        for (int c = 0; c < 16; c++) acc[i][c] = 0.0f;
    __syncthreads();

    for (int kt = 0; kt < 64; kt++) {
        const int key0 = kt << 6;

        // ---- Phase A: S = Q . K^T (scaled) ----
        float s[4][4] = {};
        for (int kk = 0; kk < EDIM; kk += 32) {
            __syncthreads();   // previous consumers of Wb done
            #pragma unroll
            for (int e = 0; e < 8; e++) {
                int idx = tid + e*256;
                int key = idx >> 5;
                int k   = idx & 31;
                Wb[k*68 + key] = Kb[(key0+key)*EDIM + kk + k];
            }
            __syncthreads();
            #pragma unroll 8
            for (int k = 0; k < 32; k++) {
                float4 a4 = *(const float4*)(Qt + (kk+k)*68 + 4*ty);
                float4 b4 = *(const float4*)(Wb + k*68 + 4*tx);
                float a[4] = {a4.x, a4.y, a4.z, a4.w};
                float bq_[4] = {b4.x, b4.y, b4.z, b4.w};
                #pragma unroll
                for (int i = 0; i < 4; i++)
                    #pragma unroll
                    for (int j = 0; j < 4; j++)
                        s[i][j] = fmaf(a[i], bq_[j], s[i][j]);
            }
        }
        // write scaled scores: scale = 1/sqrt(4096) = 1/64
        #pragma unroll
        for (int i = 0; i < 4; i++)
            #pragma unroll
            for (int j = 0; j < 4; j++)
                Ss[(4*ty+i)*65 + 4*tx+j] = s[i][j] * 0.015625f;
        __syncthreads();

        // ---- Phase B: online softmax (one thread per query row) ----
        if (tid < 64) {
            float* srow = Ss + tid*65;
            float mo = rm[tid];
            float mx = mo;
            #pragma unroll 8
            for (int c = 0; c < 64; c++) mx = fmaxf(mx, srow[c]);
            float alpha = __expf(mo - mx);
            float sum = 0.0f;
            #pragma unroll 8
            for (int c = 0; c < 64; c++) {
                float p = __expf(srow[c] - mx);
                srow[c] = p;
                sum += p;
            }
            rm[tid] = mx;
            rl[tid] = rl[tid]*alpha + sum;
            ra[tid] = alpha;
        }
        __syncthreads();

        // rescale accumulators
        float al[4];
        #pragma unroll
        for (int i = 0; i < 4; i++) al[i] = ra[4*ty+i];
        #pragma unroll
        for (int i = 0; i < 4; i++)
            #pragma unroll
            for (int c = 0; c < 16; c++) acc[i][c] *= al[i];

        // ---- Phase C: acc += P . V, 4 chunks of 64 dims ----
        #pragma unroll
        for (int dc = 0; dc < 4; dc++) {
            __syncthreads();   // previous Wb consumers done
            #pragma unroll
            for (int e = 0; e < 16; e++) {
                int idx = tid + e*256;
                int key = idx >> 6;
                int c   = idx & 63;
                Wb[key*68 + c] = Vb[(key0+key)*EDIM + (dc<<6) + c];
            }
            __syncthreads();
            #pragma unroll 8
            for (int kkey = 0; kkey < 64; kkey++) {
                float p[4];
                #pragma unroll
                for (int i = 0; i < 4; i++) p[i] = Ss[(4*ty+i)*65 + kkey];
                float4 v4 = *(const float4*)(Wb + kkey*68 + 4*tx);
                float v[4] = {v4.x, v4.y, v4.z, v4.w};
                #pragma unroll
                for (int i = 0; i < 4; i++)
                    #pragma unroll
                    for (int j = 0; j < 4; j++)
                        acc[i][dc*4+j] = fmaf(p[i], v[j], acc[i][dc*4+j]);
            }
        }
    }
    __syncthreads();

    // ---- Epilogue: o = attn/l + residual, then LayerNorm, coalesced stores ----
    // Row r's 256 dims live in the 16 tx-lanes of one half-warp -> shuffle reduce.
    #pragma unroll
    for (int i = 0; i < 4; i++) {
        const int r     = 4*ty + i;
        const float ivl = 1.0f / rl[r];
        const int row   = q0 + r;
        const float* resrow = RES + base + row*EDIM;

        float h[16];
        #pragma unroll
        for (int dc = 0; dc < 4; dc++) {
            float4 x4 = *(const float4*)(resrow + dc*64 + 4*tx);
            float xr[4] = {x4.x, x4.y, x4.z, x4.w};
            #pragma unroll
            for (int j = 0; j < 4; j++)
                h[dc*4+j] = acc[i][dc*4+j]*ivl + xr[j];
        }
        float s1 = 0.0f, s2 = 0.0f;
        #pragma unroll
        for (int c = 0; c < 16; c++) { s1 += h[c]; s2 += h[c]*h[c]; }
        #pragma unroll
        for (int off = 8; off >= 1; off >>= 1) {
            s1 += __shfl_xor_sync(0xffffffffu, s1, off);
            s2 += __shfl_xor_sync(0xffffffffu, s2, off);
        }
        const float mu  = s1 * (1.0f/256.0f);
        const float var = s2 * (1.0f/256.0f) - mu*mu;
        const float rs  = rsqrtf(var + 1e-5f);
        #pragma unroll
        for (int dc = 0; dc < 4; dc++) {
            float4 g4 = *(const float4*)(gamma + dc*64 + 4*tx);
            float4 b4 = *(const float4*)(beta  + dc*64 + 4*tx);
            float4 o;
            o.x = (h[dc*4+0]-mu)*rs*g4.x + b4.x;
            o.y = (h[dc*4+1]-mu)*rs*g4.y + b4.y;
            o.z = (h[dc*4+2]-mu)*rs*g4.z + b4.z;
            o.w = (h[dc*4+3]-mu)*rs*g4.w + b4.w;
            *(float4*)(OUT + base + row*EDIM + dc*64 + 4*tx) = o;
        }
    }
}

// ---------------------------------------------------------------------------
extern "C" void kernel_launch(void* const* d_in, const int* in_sizes, int n_in,
                              void* d_out, int out_size) {
    const float* x     = (const float*)d_in[0];
    const float* Wq1   = (const float*)d_in[1];
    const float* bq1   = (const float*)d_in[2];
    const float* Wk1   = (const float*)d_in[3];
    const float* bk1   = (const float*)d_in[4];
    const float* Wv1   = (const float*)d_in[5];
    const float* bv1   = (const float*)d_in[6];
    const float* Wq2   = (const float*)d_in[7];
    const float* bq2   = (const float*)d_in[8];
    const float* Wk2   = (const float*)d_in[9];
    const float* bk2   = (const float*)d_in[10];
    const float* Wv2   = (const float*)d_in[11];
    const float* bv2   = (const float*)d_in[12];
    const float* g1    = (const float*)d_in[13];
    const float* beta1 = (const float*)d_in[14];
    const float* g2    = (const float*)d_in[15];
    const float* beta2 = (const float*)d_in[16];
    float* out = (float*)d_out;

    float* O = nullptr;
    cudaGetSymbolAddress((void**)&O, g_O);

    const size_t smem = (size_t)(256*68 + 64*65 + 64*68 + 192) * sizeof(float); // 104448 B
    cudaFuncSetAttribute(flash_kernel, cudaFuncAttributeMaxDynamicSharedMemorySize, (int)smem);

    dim3 pg(NTOK/64, 12), pb(256);
    dim3 fg(SEQ/64, BATCH), fb(256);

    // Layer 1
    proj_kernel<<<pg, pb>>>(x, Wq1, bq1, Wk1, bk1, Wv1, bv1);
    flash_kernel<<<fg, fb, smem>>>(x, g1, beta1, O);
    // Layer 2
    proj_kernel<<<pg, pb>>>(O, Wq2, bq2, Wk2, bk2, Wv2, bv2);
    flash_kernel<<<fg, fb, smem>>>(O, g2, beta2, out);
}

// round 2
// speedup vs baseline: 1.0006x; 1.0006x over previous
#include <cuda_runtime.h>

#define BATCH 4
#define SEQ   4096
#define EDIM  256
#define NTOK  (BATCH*SEQ)

// Scratch (device globals: no allocation allowed in kernel_launch)
__device__ float g_Q[NTOK*EDIM];
__device__ float g_K[NTOK*EDIM];
__device__ float g_V[NTOK*EDIM];
__device__ float g_O[NTOK*EDIM];

// ---------------------------------------------------------------------------
// Fused QKV projection: Y[m,n] = sum_k X[m,k] * W[n,k] + b[n]
// grid = (NTOK/64, 12): blockIdx.y selects {Wq,Wk,Wv} x 4 column tiles of 64.
// CTA tile 64x64, 256 threads, 4x4 micro-tile. Smem tiles stored k-major so
// the inner loop is two float4 LDS (one warp-broadcast) per 16 FFMA.
// ---------------------------------------------------------------------------
__global__ __launch_bounds__(256) void proj_kernel(
    const float* __restrict__ X,
    const float* __restrict__ Wq, const float* __restrict__ bq,
    const float* __restrict__ Wk, const float* __restrict__ bk,
    const float* __restrict__ Wv, const float* __restrict__ bv)
{
    __shared__ __align__(16) float Xt[32*68];
    __shared__ __align__(16) float Wt[32*68];

    const int mt    = blockIdx.x;
    const int nt    = blockIdx.y;
    const int which = nt >> 2;           // 0=q 1=k 2=v
    const int n0    = (nt & 3) << 6;
    const int m0    = mt << 6;

    const float* W    = (which == 0) ? Wq : (which == 1) ? Wk : Wv;
    const float* bias = (which == 0) ? bq : (which == 1) ? bk : bv;
    float*       Y    = (which == 0) ? g_Q : (which == 1) ? g_K : g_V;

    const int tid = threadIdx.x;
    const int tx  = tid & 15;
    const int ty  = tid >> 4;

    float acc[4][4] = {};

    for (int kk = 0; kk < EDIM; kk += 32) {
        __syncthreads();
        #pragma unroll
        for (int e = 0; e < 8; e++) {
            int idx = tid + e*256;
            int m = idx >> 5;
            int k = idx & 31;
            Xt[k*68 + m] = X[(m0+m)*EDIM + kk + k];
            Wt[k*68 + m] = W[(n0+m)*EDIM + kk + k];
        }
        __syncthreads();
        #pragma unroll 8
        for (int k = 0; k < 32; k++) {
            float4 a4 = *(const float4*)(Xt + k*68 + 4*ty);
            float4 b4 = *(const float4*)(Wt + k*68 + 4*tx);
            float a[4] = {a4.x, a4.y, a4.z, a4.w};
            float b[4] = {b4.x, b4.y, b4.z, b4.w};
            #pragma unroll
            for (int i = 0; i < 4; i++)
                #pragma unroll
                for (int j = 0; j < 4; j++)
                    acc[i][j] = fmaf(a[i], b[j], acc[i][j]);
        }
    }

    float4 bv4 = *(const float4*)(bias + n0 + 4*tx);
    float bb[4] = {bv4.x, bv4.y, bv4.z, bv4.w};
    #pragma unroll
    for (int i = 0; i < 4; i++) {
        float4 o;
        o.x = acc[i][0] + bb[0];
        o.y = acc[i][1] + bb[1];
        o.z = acc[i][2] + bb[2];
        o.w = acc[i][3] + bb[3];
        *(float4*)(Y + (m0 + 4*ty + i)*EDIM + n0 + 4*tx) = o;
    }
}

// ---------------------------------------------------------------------------
// Flash attention over one batch, 64 queries per CTA, 64-key tiles,
// online softmax, fused residual-add + LayerNorm epilogue.
// Thread (tx,ty) owns query rows 4*ty+i and dim columns dc*64 + 4*tx+j.
// Smem: Qt (full Q tile, k-major), Ss (P tile), Wb (K-chunk / V-chunk work).
// ---------------------------------------------------------------------------
__global__ __launch_bounds__(256, 2) void flash_kernel(
    const float* __restrict__ RES,
    const float* __restrict__ gamma, const float* __restrict__ beta,
    float* __restrict__ OUT)
{
    extern __shared__ float sm[];
    float* Qt = sm;                 // 256*68 (k-major: Qt[k*68 + row])
    float* Ss = Qt + 256*68;        // 64*65  (Ss[row*65 + key])
    float* Wb = Ss + 64*65;         // 64*68  work tile
    float* rm = Wb + 64*68;         // running max [64]
    float* rl = rm + 64;            // running sum [64]
    float* ra = rl + 64;            // alpha      [64]

    const int qt   = blockIdx.x;
    const int b    = blockIdx.y;
    const int q0   = qt << 6;
    const int base = b * SEQ * EDIM;
    const float* Qb = g_Q + base;
    const float* Kb = g_K + base;
    const float* Vb = g_V + base;

    const int tid = threadIdx.x;
    const int tx  = tid & 15;
    const int ty  = tid >> 4;

    // Load Q tile [64 x 256] transposed to k-major (coalesced gmem reads)
    #pragma unroll 8
    for (int r = 0; r < 64; r++) {
        Qt[tid*68 + r] = Qb[(q0 + r)*EDIM + tid];
    }
    if (tid < 64) { rm[tid] = -1e30f; rl[tid] = 0.0f; }

    float acc[4][16];
    #pragma unroll
    for (int i = 0; i < 4; i++)
        #pragma unroll
        for (int c = 0; c < 16; c++) acc[i][c] = 0.0f;
    __syncthreads();

    for (int kt = 0; kt < 64; kt++) {
        const int key0 = kt << 6;

        // ---- Phase A: S = Q . K^T (scaled) ----
        float s[4][4] = {};
        for (int kk = 0; kk < EDIM; kk += 32) {
            __syncthreads();   // previous consumers of Wb done
            #pragma unroll
            for (int e = 0; e < 8; e++) {
                int idx = tid + e*256;
                int key = idx >> 5;
                int k   = idx & 31;
                Wb[k*68 + key] = Kb[(key0+key)*EDIM + kk + k];
            }
            __syncthreads();
            #pragma unroll 8
            for (int k = 0; k < 32; k++) {
                float4 a4 = *(const float4*)(Qt + (kk+k)*68 + 4*ty);
                float4 b4 = *(const float4*)(Wb + k*68 + 4*tx);
                float a[4] = {a4.x, a4.y, a4.z, a4.w};
                float bq_[4] = {b4.x, b4.y, b4.z, b4.w};
                #pragma unroll
                for (int i = 0; i < 4; i++)
                    #pragma unroll
                    for (int j = 0; j < 4; j++)
                        s[i][j] = fmaf(a[i], bq_[j], s[i][j]);
            }
        }
        // write scaled scores: scale = 1/sqrt(4096) = 1/64
        #pragma unroll
        for (int i = 0; i < 4; i++)
            #pragma unroll
            for (int j = 0; j < 4; j++)
                Ss[(4*ty+i)*65 + 4*tx+j] = s[i][j] * 0.015625f;
        __syncthreads();

        // ---- Phase B: online softmax (one thread per query row) ----
        if (tid < 64) {
            float* srow = Ss + tid*65;
            float mo = rm[tid];
            float mx = mo;
            #pragma unroll 8
            for (int c = 0; c < 64; c++) mx = fmaxf(mx, srow[c]);
            float alpha = __expf(mo - mx);
            float sum = 0.0f;
            #pragma unroll 8
            for (int c = 0; c < 64; c++) {
                float p = __expf(srow[c] - mx);
                srow[c] = p;
                sum += p;
            }
            rm[tid] = mx;
            rl[tid] = rl[tid]*alpha + sum;
            ra[tid] = alpha;
        }
        __syncthreads();

        // rescale accumulators
        float al[4];
        #pragma unroll
        for (int i = 0; i < 4; i++) al[i] = ra[4*ty+i];
        #pragma unroll
        for (int i = 0; i < 4; i++)
            #pragma unroll
            for (int c = 0; c < 16; c++) acc[i][c] *= al[i];

        // ---- Phase C: acc += P . V, 4 chunks of 64 dims ----
        #pragma unroll
        for (int dc = 0; dc < 4; dc++) {
            __syncthreads();   // previous Wb consumers done
            #pragma unroll
            for (int e = 0; e < 16; e++) {
                int idx = tid + e*256;
                int key = idx >> 6;
                int c   = idx & 63;
                Wb[key*68 + c] = Vb[(key0+key)*EDIM + (dc<<6) + c];
            }
            __syncthreads();
            #pragma unroll 8
            for (int kkey = 0; kkey < 64; kkey++) {
                float p[4];
                #pragma unroll
                for (int i = 0; i < 4; i++) p[i] = Ss[(4*ty+i)*65 + kkey];
                float4 v4 = *(const float4*)(Wb + kkey*68 + 4*tx);
                float v[4] = {v4.x, v4.y, v4.z, v4.w};
                #pragma unroll
                for (int i = 0; i < 4; i++)
                    #pragma unroll
                    for (int j = 0; j < 4; j++)
                        acc[i][dc*4+j] = fmaf(p[i], v[j], acc[i][dc*4+j]);
            }
        }
    }
    __syncthreads();

    // ---- Epilogue: o = attn/l + residual, then LayerNorm, coalesced stores ----
    // Row r's 256 dims live in the 16 tx-lanes of one half-warp -> shuffle reduce.
    #pragma unroll
    for (int i = 0; i < 4; i++) {
        const int r     = 4*ty + i;
        const float ivl = 1.0f / rl[r];
        const int row   = q0 + r;
        const float* resrow = RES + base + row*EDIM;

        float h[16];
        #pragma unroll
        for (int dc = 0; dc < 4; dc++) {
            float4 x4 = *(const float4*)(resrow + dc*64 + 4*tx);
            float xr[4] = {x4.x, x4.y, x4.z, x4.w};
            #pragma unroll
            for (int j = 0; j < 4; j++)
                h[dc*4+j] = acc[i][dc*4+j]*ivl + xr[j];
        }
        float s1 = 0.0f, s2 = 0.0f;
        #pragma unroll
        for (int c = 0; c < 16; c++) { s1 += h[c]; s2 += h[c]*h[c]; }
        #pragma unroll
        for (int off = 8; off >= 1; off >>= 1) {
            s1 += __shfl_xor_sync(0xffffffffu, s1, off);
            s2 += __shfl_xor_sync(0xffffffffu, s2, off);
        }
        const float mu  = s1 * (1.0f/256.0f);
        const float var = s2 * (1.0f/256.0f) - mu*mu;
        const float rs  = rsqrtf(var + 1e-5f);
        #pragma unroll
        for (int dc = 0; dc < 4; dc++) {
            float4 g4 = *(const float4*)(gamma + dc*64 + 4*tx);
            float4 b4 = *(const float4*)(beta  + dc*64 + 4*tx);
            float4 o;
            o.x = (h[dc*4+0]-mu)*rs*g4.x + b4.x;
            o.y = (h[dc*4+1]-mu)*rs*g4.y + b4.y;
            o.z = (h[dc*4+2]-mu)*rs*g4.z + b4.z;
            o.w = (h[dc*4+3]-mu)*rs*g4.w + b4.w;
            *(float4*)(OUT + base + row*EDIM + dc*64 + 4*tx) = o;
        }
    }
}

// ---------------------------------------------------------------------------
extern "C" void kernel_launch(void* const* d_in, const int* in_sizes, int n_in,
                              void* d_out, int out_size) {
    const float* x     = (const float*)d_in[0];
    const float* Wq1   = (const float*)d_in[1];
    const float* bq1   = (const float*)d_in[2];
    const float* Wk1   = (const float*)d_in[3];
    const float* bk1   = (const float*)d_in[4];
    const float* Wv1   = (const float*)d_in[5];
    const float* bv1   = (const float*)d_in[6];
    const float* Wq2   = (const float*)d_in[7];
    const float* bq2   = (const float*)d_in[8];
    const float* Wk2   = (const float*)d_in[9];
    const float* bk2   = (const float*)d_in[10];
    const float* Wv2   = (const float*)d_in[11];
    const float* bv2   = (const float*)d_in[12];
    const float* g1    = (const float*)d_in[13];
    const float* beta1 = (const float*)d_in[14];
    const float* g2    = (const float*)d_in[15];
    const float* beta2 = (const float*)d_in[16];
    float* out = (float*)d_out;

    float* O = nullptr;
    cudaGetSymbolAddress((void**)&O, g_O);

    const size_t smem = (size_t)(256*68 + 64*65 + 64*68 + 192) * sizeof(float); // 104448 B
    cudaFuncSetAttribute(flash_kernel, cudaFuncAttributeMaxDynamicSharedMemorySize, (int)smem);

    dim3 pg(NTOK/64, 12), pb(256);
    dim3 fg(SEQ/64, BATCH), fb(256);

    // Layer 1
    proj_kernel<<<pg, pb>>>(x, Wq1, bq1, Wk1, bk1, Wv1, bv1);
    flash_kernel<<<fg, fb, smem>>>(x, g1, beta1, O);
    // Layer 2
    proj_kernel<<<pg, pb>>>(O, Wq2, bq2, Wk2, bk2, Wv2, bv2);
    flash_kernel<<<fg, fb, smem>>>(O, g2, beta2, out);
}

// round 3
// speedup vs baseline: 2.0337x; 2.0325x over previous
#include <cuda_runtime.h>

#define BATCH 4
#define SEQ   4096
#define EDIM  256
#define NTOK  (BATCH*SEQ)

// Scratch (device globals: no allocation allowed in kernel_launch)
__device__ float g_Q[NTOK*EDIM];
__device__ float g_K[NTOK*EDIM];
__device__ float g_V[NTOK*EDIM];
__device__ float g_O[NTOK*EDIM];

// ---------------------------------------------------------------------------
// tf32 helpers
// ---------------------------------------------------------------------------
__device__ __forceinline__ unsigned f2tf(float x) {
    unsigned r;
    asm("cvt.rna.tf32.f32 %0, %1;" : "=r"(r) : "f"(x));
    return r;
}

__device__ __forceinline__ void mma_tf32(float* c,
                                         unsigned a0, unsigned a1, unsigned a2, unsigned a3,
                                         unsigned b0, unsigned b1) {
    asm volatile(
        "mma.sync.aligned.m16n8k8.row.col.f32.tf32.tf32.f32 "
        "{%0,%1,%2,%3}, {%4,%5,%6,%7}, {%8,%9}, {%0,%1,%2,%3};"
        : "+f"(c[0]), "+f"(c[1]), "+f"(c[2]), "+f"(c[3])
        : "r"(a0), "r"(a1), "r"(a2), "r"(a3), "r"(b0), "r"(b1));
}

// ---------------------------------------------------------------------------
// Fused QKV projection (unchanged from R1): Y[m,n] = sum_k X[m,k]*W[n,k] + b[n]
// ---------------------------------------------------------------------------
__global__ __launch_bounds__(256) void proj_kernel(
    const float* __restrict__ X,
    const float* __restrict__ Wq, const float* __restrict__ bq,
    const float* __restrict__ Wk, const float* __restrict__ bk,
    const float* __restrict__ Wv, const float* __restrict__ bv)
{
    __shared__ __align__(16) float Xt[32*68];
    __shared__ __align__(16) float Wt[32*68];

    const int mt    = blockIdx.x;
    const int nt    = blockIdx.y;
    const int which = nt >> 2;
    const int n0    = (nt & 3) << 6;
    const int m0    = mt << 6;

    const float* W    = (which == 0) ? Wq : (which == 1) ? Wk : Wv;
    const float* bias = (which == 0) ? bq : (which == 1) ? bk : bv;
    float*       Y    = (which == 0) ? g_Q : (which == 1) ? g_K : g_V;

    const int tid = threadIdx.x;
    const int tx  = tid & 15;
    const int ty  = tid >> 4;

    float acc[4][4] = {};

    for (int kk = 0; kk < EDIM; kk += 32) {
        __syncthreads();
        #pragma unroll
        for (int e = 0; e < 8; e++) {
            int idx = tid + e*256;
            int m = idx >> 5;
            int k = idx & 31;
            Xt[k*68 + m] = X[(m0+m)*EDIM + kk + k];
            Wt[k*68 + m] = W[(n0+m)*EDIM + kk + k];
        }
        __syncthreads();
        #pragma unroll 8
        for (int k = 0; k < 32; k++) {
            float4 a4 = *(const float4*)(Xt + k*68 + 4*ty);
            float4 b4 = *(const float4*)(Wt + k*68 + 4*tx);
            float a[4] = {a4.x, a4.y, a4.z, a4.w};
            float b[4] = {b4.x, b4.y, b4.z, b4.w};
            #pragma unroll
            for (int i = 0; i < 4; i++)
                #pragma unroll
                for (int j = 0; j < 4; j++)
                    acc[i][j] = fmaf(a[i], b[j], acc[i][j]);
        }
    }

    float4 bv4 = *(const float4*)(bias + n0 + 4*tx);
    float bb[4] = {bv4.x, bv4.y, bv4.z, bv4.w};
    #pragma unroll
    for (int i = 0; i < 4; i++) {
        float4 o;
        o.x = acc[i][0] + bb[0];
        o.y = acc[i][1] + bb[1];
        o.z = acc[i][2] + bb[2];
        o.w = acc[i][3] + bb[3];
        *(float4*)(Y + (m0 + 4*ty + i)*EDIM + n0 + 4*tx) = o;
    }
}

// ---------------------------------------------------------------------------
// tf32 mma.sync flash attention + fused residual/LayerNorm.
// CTA: 64 queries, 8 warps (256 threads), key tiles of 64, 64 tiles per batch.
//
// Smem (dynamic, float units):
//   Qs  [64][260]  tf32 Q tile, row-major (stride 260 % 32 == 4 -> A-frag cf)
//   Kt  [64][73]   tf32 K chunk, k-major (stride 73: cf transpose stores)
//   Vs  [64][264]  tf32 V tile, key-major (stride 264 % 32 == 8 -> B-frag cf)
//   Ss  [64][68]   S / P tile (stride 68 % 32 == 4 -> A-frag cf)
//   rm/rl/ra [64]  online-softmax state
// ---------------------------------------------------------------------------
#define QS_OFF 0
#define QS_STR 260
#define KT_OFF 16640
#define KT_STR 73
#define VS_OFF 21312
#define VS_STR 264
#define SS_OFF 38208
#define SS_STR 68
#define RM_OFF 42560
#define RL_OFF 42624
#define RA_OFF 42688
#define SMEM_FLOATS 42752   // 171008 bytes

__global__ __launch_bounds__(256, 1) void flash_kernel(
    const float* __restrict__ RES,
    const float* __restrict__ gamma, const float* __restrict__ beta,
    float* __restrict__ OUT)
{
    extern __shared__ float sm[];
    unsigned* QsU = (unsigned*)(sm + QS_OFF);
    unsigned* KtU = (unsigned*)(sm + KT_OFF);
    unsigned* VsU = (unsigned*)(sm + VS_OFF);
    float*    Ss  = sm + SS_OFF;
    float*    rm  = sm + RM_OFF;
    float*    rl  = sm + RL_OFF;
    float*    ra  = sm + RA_OFF;

    const int tid  = threadIdx.x;
    const int warp = tid >> 5;
    const int lane = tid & 31;
    const int ly   = lane >> 2;   // fragment row group
    const int lx   = lane & 3;    // fragment col group

    const int q0   = blockIdx.x << 6;
    const int base = blockIdx.y * SEQ * EDIM;
    const float* Qb = g_Q + base;
    const float* Kb = g_K + base;
    const float* Vb = g_V + base;

    // Phase-A warp tile: rows r0a..+15, keys n0a..+31
    const int r0a = (warp & 3) << 4;
    const int n0a = (warp >> 2) << 5;
    // Phase-C warp tile: rows r0c..+15, dims d0c..+127
    const int r0c = (warp & 3) << 4;
    const int d0c = (warp >> 2) << 7;

    // ---- Load Q tile [64 x 256] row-major, tf32-converted, coalesced ----
    #pragma unroll
    for (int i = 0; i < 16; i++) {
        int idx = tid + i*256;          // float4 index
        int row = idx >> 6;
        int c4  = (idx & 63) << 2;
        float4 q = *(const float4*)(Qb + (q0 + row)*EDIM + c4);
        unsigned* dst = QsU + row*QS_STR + c4;
        dst[0] = f2tf(q.x); dst[1] = f2tf(q.y);
        dst[2] = f2tf(q.z); dst[3] = f2tf(q.w);
    }
    if (tid < 64) { rm[tid] = -1e30f; rl[tid] = 0.0f; }

    float acc[2][8][4];
    #pragma unroll
    for (int t = 0; t < 2; t++)
        #pragma unroll
        for (int nb = 0; nb < 8; nb++)
            #pragma unroll
            for (int r = 0; r < 4; r++) acc[t][nb][r] = 0.0f;

    for (int kt = 0; kt < 64; kt++) {
        const int key0 = kt << 6;

        // ================= Phase A: S = Q . K^T (tf32 mma) =================
        float sC[4][4];
        #pragma unroll
        for (int nb = 0; nb < 4; nb++)
            #pragma unroll
            for (int r = 0; r < 4; r++) sC[nb][r] = 0.0f;

        for (int kc = 0; kc < 4; kc++) {
            __syncthreads();   // prior readers of Kt/Vs done
            // K chunk: Kt[k][key] = K[key0+key][kc*64+k], k in [0,64)
            #pragma unroll
            for (int i = 0; i < 4; i++) {
                int idx = tid + i*256;          // float4 units: 64 keys x 16
                int key = idx >> 4;
                int g   = (idx & 15) << 2;
                float4 kv = *(const float4*)(Kb + (key0 + key)*EDIM + (kc<<6) + g);
                KtU[(g+0)*KT_STR + key] = f2tf(kv.x);
                KtU[(g+1)*KT_STR + key] = f2tf(kv.y);
                KtU[(g+2)*KT_STR + key] = f2tf(kv.z);
                KtU[(g+3)*KT_STR + key] = f2tf(kv.w);
            }
            // V rows 16*kc..+15 (spread across the 4 chunks)
            #pragma unroll
            for (int i = 0; i < 4; i++) {
                int idx  = tid + i*256;         // float4 units: 16 rows x 64
                int vrow = (kc << 4) + (idx >> 6);
                int c4   = (idx & 63) << 2;
                float4 vv = *(const float4*)(Vb + (key0 + vrow)*EDIM + c4);
                unsigned* dst = VsU + vrow*VS_STR + c4;
                dst[0] = f2tf(vv.x); dst[1] = f2tf(vv.y);
                dst[2] = f2tf(vv.z); dst[3] = f2tf(vv.w);
            }
            __syncthreads();

            #pragma unroll
            for (int ks = 0; ks < 8; ks++) {
                const int kb = (kc << 6) + (ks << 3);
                unsigned a0 = QsU[(r0a + ly    )*QS_STR + kb + lx    ];
                unsigned a1 = QsU[(r0a + ly + 8)*QS_STR + kb + lx    ];
                unsigned a2 = QsU[(r0a + ly    )*QS_STR + kb + lx + 4];
                unsigned a3 = QsU[(r0a + ly + 8)*QS_STR + kb + lx + 4];
                #pragma unroll
                for (int nb = 0; nb < 4; nb++) {
                    const int n = n0a + (nb << 3) + ly;
                    unsigned b0 = KtU[((ks<<3) + lx    )*KT_STR + n];
                    unsigned b1 = KtU[((ks<<3) + lx + 4)*KT_STR + n];
                    mma_tf32(sC[nb], a0, a1, a2, a3, b0, b1);
                }
            }
        }

        // store scaled scores to Ss (scale = 1/sqrt(4096) = 1/64)
        {
            const float scale = 0.015625f;
            #pragma unroll
            for (int nb = 0; nb < 4; nb++) {
                const int col = n0a + (nb << 3) + (lx << 1);
                *(float2*)(Ss + (r0a + ly    )*SS_STR + col) =
                    make_float2(sC[nb][0]*scale, sC[nb][1]*scale);
                *(float2*)(Ss + (r0a + ly + 8)*SS_STR + col) =
                    make_float2(sC[nb][2]*scale, sC[nb][3]*scale);
            }
        }
        __syncthreads();

        // ================= Phase B: online softmax (4 threads/row) ==========
        {
            const int row = tid >> 2;
            const int qq  = tid & 3;
            float* srow = Ss + row*SS_STR + (qq << 4);
            float4 v0 = *(float4*)(srow + 0);
            float4 v1 = *(float4*)(srow + 4);
            float4 v2 = *(float4*)(srow + 8);
            float4 v3 = *(float4*)(srow + 12);
            float mo = rm[row];
            float mx = fmaxf(fmaxf(fmaxf(v0.x, v0.y), fmaxf(v0.z, v0.w)),
                             fmaxf(fmaxf(v1.x, v1.y), fmaxf(v1.z, v1.w)));
            mx = fmaxf(mx, fmaxf(fmaxf(fmaxf(v2.x, v2.y), fmaxf(v2.z, v2.w)),
                                 fmaxf(fmaxf(v3.x, v3.y), fmaxf(v3.z, v3.w))));
            mx = fmaxf(mx, __shfl_xor_sync(0xffffffffu, mx, 1));
            mx = fmaxf(mx, __shfl_xor_sync(0xffffffffu, mx, 2));
            mx = fmaxf(mx, mo);
            v0.x = __expf(v0.x - mx); v0.y = __expf(v0.y - mx);
            v0.z = __expf(v0.z - mx); v0.w = __expf(v0.w - mx);
            v1.x = __expf(v1.x - mx); v1.y = __expf(v1.y - mx);
            v1.z = __expf(v1.z - mx); v1.w = __expf(v1.w - mx);
            v2.x = __expf(v2.x - mx); v2.y = __expf(v2.y - mx);
            v2.z = __expf(v2.z - mx); v2.w = __expf(v2.w - mx);
            v3.x = __expf(v3.x - mx); v3.y = __expf(v3.y - mx);
            v3.z = __expf(v3.z - mx); v3.w = __expf(v3.w - mx);
            float s = v0.x+v0.y+v0.z+v0.w + v1.x+v1.y+v1.z+v1.w
                    + v2.x+v2.y+v2.z+v2.w + v3.x+v3.y+v3.z+v3.w;
            s += __shfl_xor_sync(0xffffffffu, s, 1);
            s += __shfl_xor_sync(0xffffffffu, s, 2);
            *(float4*)(srow + 0)  = v0;
            *(float4*)(srow + 4)  = v1;
            *(float4*)(srow + 8)  = v2;
            *(float4*)(srow + 12) = v3;
            if (qq == 0) {
                float alpha = __expf(mo - mx);
                rm[row] = mx;
                rl[row] = rl[row]*alpha + s;
                ra[row] = alpha;
            }
        }
        __syncthreads();

        // ================= Phase C: O += P . V (tf32 mma) ===================
        {
            float al0 = ra[r0c + ly];
            float al1 = ra[r0c + ly + 8];
            #pragma unroll
            for (int t = 0; t < 2; t++)
                #pragma unroll
                for (int nb = 0; nb < 8; nb++) {
                    acc[t][nb][0] *= al0; acc[t][nb][1] *= al0;
                    acc[t][nb][2] *= al1; acc[t][nb][3] *= al1;
                }
        }
        const unsigned* SsU = (const unsigned*)Ss;
        #pragma unroll
        for (int ks = 0; ks < 8; ks++) {
            unsigned a0 = SsU[(r0c + ly    )*SS_STR + (ks<<3) + lx    ];
            unsigned a1 = SsU[(r0c + ly + 8)*SS_STR + (ks<<3) + lx    ];
            unsigned a2 = SsU[(r0c + ly    )*SS_STR + (ks<<3) + lx + 4];
            unsigned a3 = SsU[(r0c + ly + 8)*SS_STR + (ks<<3) + lx + 4];
            #pragma unroll
            for (int t = 0; t < 2; t++)
                #pragma unroll
                for (int nb = 0; nb < 8; nb++) {
                    const int n = d0c + (t << 6) + (nb << 3) + ly;
                    unsigned b0 = VsU[((ks<<3) + lx    )*VS_STR + n];
                    unsigned b1 = VsU[((ks<<3) + lx + 4)*VS_STR + n];
                    mma_tf32(acc[t][nb], a0, a1, a2, a3, b0, b1);
                }
        }
    }
    __syncthreads();

    // ---- Epilogue: scatter h = acc/rl into Vs, then residual + LayerNorm ----
    float* Vf = sm + VS_OFF;
    {
        float il0 = 1.0f / rl[r0c + ly];
        float il1 = 1.0f / rl[r0c + ly + 8];
        #pragma unroll
        for (int t = 0; t < 2; t++)
            #pragma unroll
            for (int nb = 0; nb < 8; nb++) {
                const int n = d0c + (t << 6) + (nb << 3) + (lx << 1);
                *(float2*)(Vf + (r0c + ly    )*VS_STR + n) =
                    make_float2(acc[t][nb][0]*il0, acc[t][nb][1]*il0);
                *(float2*)(Vf + (r0c + ly + 8)*VS_STR + n) =
                    make_float2(acc[t][nb][2]*il1, acc[t][nb][3]*il1);
            }
    }
    __syncthreads();

    #pragma unroll
    for (int rr = 0; rr < 8; rr++) {
        const int row = (warp << 3) + rr;
        const int d   = lane << 3;
        float4 h0 = *(float4*)(Vf + row*VS_STR + d);
        float4 h1 = *(float4*)(Vf + row*VS_STR + d + 4);
        const float* resrow = RES + base + (q0 + row)*EDIM + d;
        float4 x0 = *(const float4*)(resrow);
        float4 x1 = *(const float4*)(resrow + 4);
        h0.x += x0.x; h0.y += x0.y; h0.z += x0.z; h0.w += x0.w;
        h1.x += x1.x; h1.y += x1.y; h1.z += x1.z; h1.w += x1.w;
        float s1 = h0.x+h0.y+h0.z+h0.w + h1.x+h1.y+h1.z+h1.w;
        float s2 = h0.x*h0.x + h0.y*h0.y + h0.z*h0.z + h0.w*h0.w
                 + h1.x*h1.x + h1.y*h1.y + h1.z*h1.z + h1.w*h1.w;
        #pragma unroll
        for (int off = 16; off >= 1; off >>= 1) {
            s1 += __shfl_xor_sync(0xffffffffu, s1, off);
            s2 += __shfl_xor_sync(0xffffffffu, s2, off);
        }
        const float mu  = s1 * (1.0f/256.0f);
        const float var = s2 * (1.0f/256.0f) - mu*mu;
        const float rs  = rsqrtf(var + 1e-5f);
        float4 g0 = *(const float4*)(gamma + d);
        float4 g1 = *(const float4*)(gamma + d + 4);
        float4 b0 = *(const float4*)(beta + d);
        float4 b1 = *(const float4*)(beta + d + 4);
        float4 o0, o1;
        o0.x = (h0.x-mu)*rs*g0.x + b0.x;  o0.y = (h0.y-mu)*rs*g0.y + b0.y;
        o0.z = (h0.z-mu)*rs*g0.z + b0.z;  o0.w = (h0.w-mu)*rs*g0.w + b0.w;
        o1.x = (h1.x-mu)*rs*g1.x + b1.x;  o1.y = (h1.y-mu)*rs*g1.y + b1.y;
        o1.z = (h1.z-mu)*rs*g1.z + b1.z;  o1.w = (h1.w-mu)*rs*g1.w + b1.w;
        float* orow = OUT + base + (q0 + row)*EDIM + d;
        *(float4*)(orow)     = o0;
        *(float4*)(orow + 4) = o1;
    }
}

// ---------------------------------------------------------------------------
extern "C" void kernel_launch(void* const* d_in, const int* in_sizes, int n_in,
                              void* d_out, int out_size) {
    const float* x     = (const float*)d_in[0];
    const float* Wq1   = (const float*)d_in[1];
    const float* bq1   = (const float*)d_in[2];
    const float* Wk1   = (const float*)d_in[3];
    const float* bk1   = (const float*)d_in[4];
    const float* Wv1   = (const float*)d_in[5];
    const float* bv1   = (const float*)d_in[6];
    const float* Wq2   = (const float*)d_in[7];
    const float* bq2   = (const float*)d_in[8];
    const float* Wk2   = (const float*)d_in[9];
    const float* bk2   = (const float*)d_in[10];
    const float* Wv2   = (const float*)d_in[11];
    const float* bv2   = (const float*)d_in[12];
    const float* g1    = (const float*)d_in[13];
    const float* beta1 = (const float*)d_in[14];
    const float* g2    = (const float*)d_in[15];
    const float* beta2 = (const float*)d_in[16];
    float* out = (float*)d_out;

    float* O = nullptr;
    cudaGetSymbolAddress((void**)&O, g_O);

    const size_t smem = (size_t)SMEM_FLOATS * sizeof(float); // 171008 B
    cudaFuncSetAttribute(flash_kernel, cudaFuncAttributeMaxDynamicSharedMemorySize, (int)smem);

    dim3 pg(NTOK/64, 12), pb(256);
    dim3 fg(SEQ/64, BATCH), fb(256);

    // Layer 1
    proj_kernel<<<pg, pb>>>(x, Wq1, bq1, Wk1, bk1, Wv1, bv1);
    flash_kernel<<<fg, fb, smem>>>(x, g1, beta1, O);
    // Layer 2
    proj_kernel<<<pg, pb>>>(O, Wq2, bq2, Wk2, bk2, Wv2, bv2);
    flash_kernel<<<fg, fb, smem>>>(O, g2, beta2, out);
}